// round 1
// baseline (speedup 1.0000x reference)
#include <cuda_runtime.h>
#include <cstdint>
#include <cstddef>

// ---------------- problem constants ----------------
#define NNODE  150000
#define DIMX   64
#define N64    (NNODE * 64)          // 9,600,000
#define TDIM   384                   // 2*LAYERS*DIM
#define BATCH  1024
#define SEQ    20
#define NPRED  20

// ---------------- scratch (device globals; no runtime alloc allowed) ----------------
__device__ float g_y[4ull * N64];            // y_b = x @ basis_b   [4][N][64]  (153.6 MB)
__device__ float g_agg[N64];                 // agg accumulator     [N][64]
__device__ float g_x[N64];                   // current node state  [N][64]
__device__ float g_cs[(size_t)NNODE * TDIM]; // concat of 6 states  [N][384]    (230.4 MB)
__device__ float g_ssum[BATCH * TDIM];       // per-batch sequence sums

// ---------------- f32x2 helpers (sm_100+ packed fp32) ----------------
__device__ __forceinline__ unsigned long long dup_f32x2(float v) {
    unsigned long long a;
    asm("mov.b64 %0, {%1, %1};" : "=l"(a) : "f"(v));
    return a;
}
__device__ __forceinline__ void ffma2(unsigned long long& acc,
                                      unsigned long long a, unsigned long long b) {
    asm("fma.rn.f32x2 %0, %1, %2, %0;" : "+l"(acc) : "l"(a), "l"(b));
}

// =====================================================================
// Dense kernel: for 64-row tile, compute y_b = x@basis_b (b=0..3) and
// agg = x@root + bias.  Treated as [64x64] @ [64x320] GEMM.
// 256 threads: tr = t>>5 (8 row-groups of 8 rows), tc = t&31 (col pairs).
// Thread owns 8 rows x 5 col-pairs (cols 2*tc + 64*jj, matrix m == jj).
// f32x2 packed FMA doubles fp32 throughput.
// =====================================================================
__global__ __launch_bounds__(256) void dense_kernel(
    const float* __restrict__ xin,   // nullptr -> read g_x
    const float* __restrict__ basis, // [4][64][64] layer slice
    const float* __restrict__ root,  // [64][64]
    const float* __restrict__ bias)  // [64]
{
    __shared__ float xs[64][17];      // x tile [row][k-chunk], padded
    __shared__ float Ws[16 * 320];    // W chunk [k][320]  (20 KB)

    const float* xp = (xin == nullptr) ? g_x : xin;

    int t  = threadIdx.x;
    int tr = t >> 5;
    int tc = t & 31;
    int row0 = blockIdx.x * 64;

    unsigned long long acc[8][5];
#pragma unroll
    for (int i = 0; i < 8; i++)
#pragma unroll
        for (int j = 0; j < 5; j++) acc[i][j] = 0ull;

    for (int c = 0; c < 4; ++c) {
        int k0 = c * 16;
        // --- load x chunk: 64 rows x 16 k ---
        {
            int r = t >> 2;
            int q = (t & 3) * 4;
            int grow = row0 + r;
            float4 v = make_float4(0.f, 0.f, 0.f, 0.f);
            if (grow < NNODE)
                v = *reinterpret_cast<const float4*>(xp + (size_t)grow * 64 + k0 + q);
            xs[r][q + 0] = v.x; xs[r][q + 1] = v.y;
            xs[r][q + 2] = v.z; xs[r][q + 3] = v.w;
        }
        // --- load W chunk: 16 k x 320 cols (basis0..3 | root) ---
#pragma unroll
        for (int i = 0; i < 20; i++) {
            int idx = t + 256 * i;                // 0..5119
            int kl  = idx / 320;
            int col = idx - kl * 320;
            int m   = col >> 6;
            int e   = col & 63;
            float v = (m < 4) ? basis[m * 4096 + (k0 + kl) * 64 + e]
                              : root[(k0 + kl) * 64 + e];
            Ws[idx] = v;
        }
        __syncthreads();

#pragma unroll
        for (int kk = 0; kk < 16; ++kk) {
            unsigned long long w[5];
#pragma unroll
            for (int jj = 0; jj < 5; jj++)
                w[jj] = *reinterpret_cast<const unsigned long long*>(
                            &Ws[kk * 320 + 2 * tc + 64 * jj]);
#pragma unroll
            for (int i = 0; i < 8; i++) {
                unsigned long long a = dup_f32x2(xs[tr * 8 + i][kk]);
#pragma unroll
                for (int jj = 0; jj < 5; jj++) ffma2(acc[i][jj], a, w[jj]);
            }
        }
        __syncthreads();
    }

    // --- epilogue ---
    float b0 = bias[2 * tc];
    float b1 = bias[2 * tc + 1];
#pragma unroll
    for (int i = 0; i < 8; i++) {
        int row = row0 + tr * 8 + i;
        if (row < NNODE) {
#pragma unroll
            for (int jj = 0; jj < 5; jj++) {
                float2 v = *reinterpret_cast<float2*>(&acc[i][jj]);
                if (jj < 4) {
                    *reinterpret_cast<float2*>(
                        &g_y[(size_t)jj * N64 + (size_t)row * 64 + 2 * tc]) = v;
                } else {
                    v.x += b0; v.y += b1;
                    *reinterpret_cast<float2*>(
                        &g_agg[(size_t)row * 64 + 2 * tc]) = v;
                }
            }
        }
    }
}

// =====================================================================
// Edge kernel: one warp per edge.
//   msg = sum_b comp[et][b] * y_b[src]   (64 floats, 2 per lane)
//   atomicAdd(float2) into agg[dst]
// =====================================================================
__global__ __launch_bounds__(256) void edge_kernel(
    const float* __restrict__ comp,   // [8][4] layer slice
    const int* __restrict__ src,
    const int* __restrict__ dst,
    const int* __restrict__ et,
    int E)
{
    int e = blockIdx.x * 8 + (threadIdx.x >> 5);
    if (e >= E) return;
    int lane = threadIdx.x & 31;

    int s  = __ldg(&src[e]);
    int d  = __ldg(&dst[e]);
    int ty = __ldg(&et[e]);

    float c0 = __ldg(&comp[ty * 4 + 0]);
    float c1 = __ldg(&comp[ty * 4 + 1]);
    float c2 = __ldg(&comp[ty * 4 + 2]);
    float c3 = __ldg(&comp[ty * 4 + 3]);

    size_t so = (size_t)s * 64 + 2 * lane;
    float2 v0 = __ldg(reinterpret_cast<const float2*>(&g_y[0ull * N64 + so]));
    float2 v1 = __ldg(reinterpret_cast<const float2*>(&g_y[1ull * N64 + so]));
    float2 v2 = __ldg(reinterpret_cast<const float2*>(&g_y[2ull * N64 + so]));
    float2 v3 = __ldg(reinterpret_cast<const float2*>(&g_y[3ull * N64 + so]));

    float2 m;
    m.x = c0 * v0.x + c1 * v1.x + c2 * v2.x + c3 * v3.x;
    m.y = c0 * v0.y + c1 * v1.y + c2 * v2.y + c3 * v3.y;

    atomicAdd(reinterpret_cast<float2*>(&g_agg[(size_t)d * 64 + 2 * lane]), m);
}

// =====================================================================
// Finish: x = tanh(agg); also append into concat buffer cs.
// =====================================================================
__global__ __launch_bounds__(256) void finish_kernel(int loff)
{
    int idx = blockIdx.x * 256 + threadIdx.x;
    if (idx >= N64) return;
    float v = tanhf(g_agg[idx]);
    g_x[idx] = v;
    int n = idx >> 6;
    int j = idx & 63;
    g_cs[(size_t)n * TDIM + loff + j] = v;
}

// =====================================================================
// Tail A: gather item_embs_conv + user_emb outputs, build sequence sums.
// grid = BATCH blocks, TDIM threads (thread == output column).
// =====================================================================
__global__ __launch_bounds__(TDIM) void tail_a(
    const int* __restrict__ users,
    const int* __restrict__ seqs,
    float* __restrict__ out_user,   // [BATCH][TDIM]
    float* __restrict__ out_item)   // [BATCH][SEQ][TDIM]
{
    int b = blockIdx.x;
    int t = threadIdx.x;
    float s = 0.f;
#pragma unroll
    for (int j = 0; j < SEQ; j++) {
        int node = __ldg(&seqs[b * SEQ + j]);
        float v  = __ldg(&g_cs[(size_t)node * TDIM + t]);
        out_item[((size_t)b * SEQ + j) * TDIM + t] = v;
        s += v;
    }
    g_ssum[b * TDIM + t] = s;
    int u = __ldg(&users[b]);
    out_user[b * TDIM + t] = __ldg(&g_cs[(size_t)u * TDIM + t]);
}

// =====================================================================
// Tail B: vsum = ssum @ WV ; uv = user_emb + vsum ;
//         res[b,k] = pe_w[item]·uv + pe_b[item]
// (attention collapses: softmax over query axis => column sums == 1)
// =====================================================================
__global__ __launch_bounds__(TDIM) void tail_b(
    const float* __restrict__ WV,        // [TDIM][TDIM]
    const float* __restrict__ predict_w, // [NITEM][TDIM]
    const float* __restrict__ predict_b, // [NITEM]
    const int*   __restrict__ items,     // [BATCH][NPRED]
    const float* __restrict__ user_emb,  // [BATCH][TDIM] (already in d_out)
    float* __restrict__ res)             // [BATCH][NPRED]
{
    __shared__ float ss[TDIM];
    __shared__ float uv[TDIM];
    int b = blockIdx.x;
    int t = threadIdx.x;

    ss[t] = g_ssum[b * TDIM + t];
    __syncthreads();

    float acc = 0.f;
#pragma unroll 8
    for (int d = 0; d < TDIM; d++)
        acc += ss[d] * __ldg(&WV[d * TDIM + t]);
    uv[t] = acc + user_emb[b * TDIM + t];
    __syncthreads();

    int w    = t >> 5;
    int lane = t & 31;
    for (int k = w; k < NPRED; k += TDIM / 32) {
        int it = __ldg(&items[b * NPRED + k]);
        const float* pw = predict_w + (size_t)it * TDIM;
        float s = 0.f;
#pragma unroll
        for (int c = lane; c < TDIM; c += 32) s += __ldg(&pw[c]) * uv[c];
#pragma unroll
        for (int off = 16; off > 0; off >>= 1)
            s += __shfl_down_sync(0xffffffffu, s, off);
        if (lane == 0)
            res[b * NPRED + k] = s + __ldg(&predict_b[it]);
    }
}

// =====================================================================
// Launch
// =====================================================================
extern "C" void kernel_launch(void* const* d_in, const int* in_sizes, int n_in,
                              void* d_out, int out_size)
{
    const float* node_emb  = (const float*)d_in[0];
    const float* predict_w = (const float*)d_in[1];
    const float* predict_b = (const float*)d_in[2];
    const float* basis     = (const float*)d_in[3];
    const float* comp      = (const float*)d_in[4];
    const float* root      = (const float*)d_in[5];
    const float* bias      = (const float*)d_in[6];
    const float* sbasis    = (const float*)d_in[7];
    const float* scomp     = (const float*)d_in[8];
    const float* sroot     = (const float*)d_in[9];
    const float* sbias     = (const float*)d_in[10];
    // d_in[11] = WQ, d_in[12] = WK  : provably unused (softmax over query axis)
    const float* WV        = (const float*)d_in[13];
    const int* batch_users = (const int*)d_in[14];
    const int* batch_seq   = (const int*)d_in[15];
    const int* items       = (const int*)d_in[16];
    const int* edge_index  = (const int*)d_in[17];
    const int* edge_type   = (const int*)d_in[18];
    // d_in[19] = node_no (arange -> identity gather, unused)
    const int* sedge_index = (const int*)d_in[20];
    const int* sedge_type  = (const int*)d_in[21];

    const int E  = in_sizes[18];   // 1,000,000
    const int SE = in_sizes[21];   //   200,000

    float* out_res  = (float*)d_out;                       // [1024][20]
    float* out_user = out_res + BATCH * NPRED;             // [1024][384]
    float* out_item = out_user + BATCH * TDIM;             // [1024][20][384]

    const int dense_grid  = (NNODE + 63) / 64;             // 2344
    const int finish_grid = (N64 + 255) / 256;

    for (int l = 0; l < 6; ++l) {
        bool big = (l < 3);
        int  ll  = big ? l : l - 3;
        const float* B  = (big ? basis  : sbasis) + ll * 16384;
        const float* R  = (big ? root   : sroot)  + ll * 4096;
        const float* Bi = (big ? bias   : sbias)  + ll * 64;
        const float* C  = (big ? comp   : scomp)  + ll * 32;
        const int* srcs = big ? edge_index  : sedge_index;
        const int* tys  = big ? edge_type   : sedge_type;
        int Ecur        = big ? E : SE;
        const int* dsts = srcs + Ecur;

        dense_kernel<<<dense_grid, 256>>>(l == 0 ? node_emb : nullptr, B, R, Bi);
        edge_kernel<<<(Ecur + 7) / 8, 256>>>(C, srcs, dsts, tys, Ecur);
        finish_kernel<<<finish_grid, 256>>>(l * 64);
    }

    tail_a<<<BATCH, TDIM>>>(batch_users, batch_seq, out_user, out_item);
    tail_b<<<BATCH, TDIM>>>(WV, predict_w, predict_b, items, out_user, out_res);
}

// round 3
// speedup vs baseline: 1.3159x; 1.3159x over previous
#include <cuda_runtime.h>
#include <cstdint>
#include <cstddef>

// ---------------- problem constants ----------------
#define NNODE  150000
#define N64    (NNODE * 64)          // 9,600,000
#define TDIM   384                   // 2*LAYERS*DIM
#define BATCH  1024
#define SEQ    20
#define NPRED  20

// ---------------- scratch (device globals; no runtime alloc allowed) ----------------
__device__ float g_xw[8ull * N64];           // xw_r = x @ W_r   [N][8][64]  (307 MB)
__device__ float g_agg[N64];                 // agg accumulator  [N][64]
__device__ float g_cs[(size_t)NNODE * TDIM]; // concat of 6 states [N][384]  (230 MB)
__device__ float g_ssum[BATCH * TDIM];       // per-batch sequence sums

// ---------------- f32x2 helpers (sm_100+ packed fp32) ----------------
__device__ __forceinline__ unsigned long long dup_f32x2(float v) {
    unsigned long long a;
    asm("mov.b64 %0, {%1, %1};" : "=l"(a) : "f"(v));
    return a;
}
__device__ __forceinline__ void ffma2(unsigned long long& acc,
                                      unsigned long long a, unsigned long long b) {
    asm("fma.rn.f32x2 %0, %1, %2, %0;" : "+l"(acc) : "l"(a), "l"(b));
}

// smem layout for dense kernel
#define WS_ELEMS (64 * 320)          // W  [k][320]  (basis0..3 | root)
#define XS_LD    68                  // padded row for transposed x tile
#define XS_ELEMS (64 * XS_LD)        // x  [k][row]
#define DENSE_SMEM ((WS_ELEMS + XS_ELEMS) * 4)   // 99,328 B

// =====================================================================
// Dense kernel: 64-row tile. acc_b = x@basis_b (b=0..3), acc_root = x@root.
// Barrier-free mainloop over all 64 k. Epilogue folds comp:
//   xw_r = sum_b comp[r,b]*acc_b  -> g_xw[row][r][:]
//   g_agg = acc_root + bias
// =====================================================================
__global__ __launch_bounds__(256, 1) void dense_kernel(
    const float* __restrict__ xin,   // nullptr -> read g_cs slice
    int layer,                       // for g_cs column offset
    const float* __restrict__ basis, // [4][64][64] layer slice
    const float* __restrict__ root,  // [64][64]
    const float* __restrict__ bias,  // [64]
    const float* __restrict__ comp)  // [8][4] layer slice
{
    extern __shared__ float sm[];
    float* Ws = sm;                   // [64][320]
    float* Xs = sm + WS_ELEMS;        // [64][XS_LD]

    const float* xp;
    int xstride;
    if (xin != nullptr) { xp = xin; xstride = 64; }
    else               { xp = g_cs + (layer - 1) * 64; xstride = TDIM; }

    int t  = threadIdx.x;
    int tr = t >> 5;
    int tc = t & 31;
    int row0 = blockIdx.x * 64;

    // ---- preload W: 5120 float4 (basis 4096 + root 1024) ----
#pragma unroll
    for (int i = 0; i < 20; i++) {
        int idx = t + 256 * i;
        float4 v; int k, col4;
        if (idx < 4096) {
            int m = idx >> 10, rem = idx & 1023;
            k = rem >> 4; int e4 = rem & 15;
            v = *reinterpret_cast<const float4*>(basis + m * 4096 + k * 64 + e4 * 4);
            col4 = m * 16 + e4;
        } else {
            int rem = idx - 4096;
            k = rem >> 4; int e4 = rem & 15;
            v = *reinterpret_cast<const float4*>(root + k * 64 + e4 * 4);
            col4 = 64 + e4;
        }
        *reinterpret_cast<float4*>(Ws + k * 320 + col4 * 4) = v;
    }
    // ---- preload x tile transposed: Xs[k][row] ----
#pragma unroll
    for (int i = 0; i < 4; i++) {
        int idx = t + 256 * i;            // 0..1023
        int row = idx >> 4;
        int kq  = (idx & 15) * 4;
        int gr  = row0 + row;
        float4 v = make_float4(0.f, 0.f, 0.f, 0.f);
        if (gr < NNODE)
            v = *reinterpret_cast<const float4*>(xp + (size_t)gr * xstride + kq);
        Xs[(kq + 0) * XS_LD + row] = v.x;
        Xs[(kq + 1) * XS_LD + row] = v.y;
        Xs[(kq + 2) * XS_LD + row] = v.z;
        Xs[(kq + 3) * XS_LD + row] = v.w;
    }
    __syncthreads();

    unsigned long long acc[8][5];
#pragma unroll
    for (int i = 0; i < 8; i++)
#pragma unroll
        for (int j = 0; j < 5; j++) acc[i][j] = 0ull;

    // ---- barrier-free mainloop over k ----
#pragma unroll 8
    for (int k = 0; k < 64; ++k) {
        unsigned long long w[5];
#pragma unroll
        for (int jj = 0; jj < 5; jj++)
            w[jj] = *reinterpret_cast<const unsigned long long*>(
                        Ws + k * 320 + 64 * jj + 2 * tc);
        float4 xa = *reinterpret_cast<const float4*>(Xs + k * XS_LD + tr * 8);
        float4 xb = *reinterpret_cast<const float4*>(Xs + k * XS_LD + tr * 8 + 4);
        float xv[8] = {xa.x, xa.y, xa.z, xa.w, xb.x, xb.y, xb.z, xb.w};
#pragma unroll
        for (int i = 0; i < 8; i++) {
            unsigned long long a = dup_f32x2(xv[i]);
#pragma unroll
            for (int jj = 0; jj < 5; jj++) ffma2(acc[i][jj], a, w[jj]);
        }
    }

    // ---- epilogue ----
    float4 cr[8];
#pragma unroll
    for (int r = 0; r < 8; r++)
        cr[r] = *reinterpret_cast<const float4*>(comp + r * 4);
    float b0 = bias[2 * tc];
    float b1 = bias[2 * tc + 1];

#pragma unroll
    for (int i = 0; i < 8; i++) {
        int row = row0 + tr * 8 + i;
        if (row >= NNODE) break;
        float2 rv = *reinterpret_cast<float2*>(&acc[i][4]);
        rv.x += b0; rv.y += b1;
        *reinterpret_cast<float2*>(g_agg + (size_t)row * 64 + 2 * tc) = rv;
#pragma unroll
        for (int r = 0; r < 8; r++) {
            unsigned long long m = 0ull;
            ffma2(m, dup_f32x2(cr[r].x), acc[i][0]);
            ffma2(m, dup_f32x2(cr[r].y), acc[i][1]);
            ffma2(m, dup_f32x2(cr[r].z), acc[i][2]);
            ffma2(m, dup_f32x2(cr[r].w), acc[i][3]);
            *reinterpret_cast<float2*>(
                g_xw + (size_t)row * 512 + r * 64 + 2 * tc) =
                *reinterpret_cast<float2*>(&m);
        }
    }
}

// =====================================================================
// Edge kernel: 16 lanes per edge. Gather one contiguous 256B row of
// xw[src][et] and atomicAdd(float4) into agg[dst].
// =====================================================================
__global__ __launch_bounds__(256) void edge_kernel(
    const int* __restrict__ src,
    const int* __restrict__ dst,
    const int* __restrict__ et,
    int E)
{
    int e = blockIdx.x * 16 + (threadIdx.x >> 4);
    if (e >= E) return;
    int j = threadIdx.x & 15;

    int s  = __ldg(&src[e]);
    int d  = __ldg(&dst[e]);
    int ty = __ldg(&et[e]);

    float4 v = __ldg(reinterpret_cast<const float4*>(
                   g_xw + (size_t)s * 512 + ty * 64 + j * 4));
    atomicAdd(reinterpret_cast<float4*>(g_agg + (size_t)d * 64 + j * 4), v);
}

// =====================================================================
// Finish: cs[:, loff:loff+64] = tanh(agg)   (float4 vectorized)
// =====================================================================
__global__ __launch_bounds__(256) void finish_kernel(int loff)
{
    int idx4 = blockIdx.x * 256 + threadIdx.x;
    if (idx4 >= N64 / 4) return;
    float4 v = *reinterpret_cast<const float4*>(g_agg + (size_t)idx4 * 4);
    v.x = tanhf(v.x); v.y = tanhf(v.y); v.z = tanhf(v.z); v.w = tanhf(v.w);
    int n  = idx4 >> 4;
    int jj = (idx4 & 15) * 4;
    *reinterpret_cast<float4*>(g_cs + (size_t)n * TDIM + loff + jj) = v;
}

// =====================================================================
// Tail A: gather item_embs_conv + user_emb outputs, build sequence sums.
// =====================================================================
__global__ __launch_bounds__(TDIM) void tail_a(
    const int* __restrict__ users,
    const int* __restrict__ seqs,
    float* __restrict__ out_user,   // [BATCH][TDIM]
    float* __restrict__ out_item)   // [BATCH][SEQ][TDIM]
{
    int b = blockIdx.x;
    int t = threadIdx.x;
    float s = 0.f;
#pragma unroll
    for (int j = 0; j < SEQ; j++) {
        int node = __ldg(&seqs[b * SEQ + j]);
        float v  = __ldg(&g_cs[(size_t)node * TDIM + t]);
        out_item[((size_t)b * SEQ + j) * TDIM + t] = v;
        s += v;
    }
    g_ssum[b * TDIM + t] = s;
    int u = __ldg(&users[b]);
    out_user[b * TDIM + t] = __ldg(&g_cs[(size_t)u * TDIM + t]);
}

// =====================================================================
// Tail B: vsum = ssum @ WV ; uv = user_emb + vsum ;
//         res[b,k] = pe_w[item]·uv + pe_b[item]
// (attention collapses: softmax over query axis => column sums == 1)
// =====================================================================
__global__ __launch_bounds__(TDIM) void tail_b(
    const float* __restrict__ WV,        // [TDIM][TDIM]
    const float* __restrict__ predict_w, // [NITEM][TDIM]
    const float* __restrict__ predict_b, // [NITEM]
    const int*   __restrict__ items,     // [BATCH][NPRED]
    const float* __restrict__ user_emb,  // [BATCH][TDIM] (already in d_out)
    float* __restrict__ res)             // [BATCH][NPRED]
{
    __shared__ float ss[TDIM];
    __shared__ float uv[TDIM];
    int b = blockIdx.x;
    int t = threadIdx.x;

    ss[t] = g_ssum[b * TDIM + t];
    __syncthreads();

    float acc = 0.f;
#pragma unroll 8
    for (int d = 0; d < TDIM; d++)
        acc += ss[d] * __ldg(&WV[d * TDIM + t]);
    uv[t] = acc + user_emb[b * TDIM + t];
    __syncthreads();

    int w    = t >> 5;
    int lane = t & 31;
    for (int k = w; k < NPRED; k += TDIM / 32) {
        int it = __ldg(&items[b * NPRED + k]);
        const float* pw = predict_w + (size_t)it * TDIM;
        float s = 0.f;
#pragma unroll
        for (int c = lane; c < TDIM; c += 32) s += __ldg(&pw[c]) * uv[c];
#pragma unroll
        for (int off = 16; off > 0; off >>= 1)
            s += __shfl_down_sync(0xffffffffu, s, off);
        if (lane == 0)
            res[b * NPRED + k] = s + __ldg(&predict_b[it]);
    }
}

// =====================================================================
// Launch
// =====================================================================
extern "C" void kernel_launch(void* const* d_in, const int* in_sizes, int n_in,
                              void* d_out, int out_size)
{
    const float* node_emb  = (const float*)d_in[0];
    const float* predict_w = (const float*)d_in[1];
    const float* predict_b = (const float*)d_in[2];
    const float* basis     = (const float*)d_in[3];
    const float* comp      = (const float*)d_in[4];
    const float* root      = (const float*)d_in[5];
    const float* bias      = (const float*)d_in[6];
    const float* sbasis    = (const float*)d_in[7];
    const float* scomp     = (const float*)d_in[8];
    const float* sroot     = (const float*)d_in[9];
    const float* sbias     = (const float*)d_in[10];
    // d_in[11] = WQ, d_in[12] = WK : provably unused (softmax over query axis)
    const float* WV        = (const float*)d_in[13];
    const int* batch_users = (const int*)d_in[14];
    const int* batch_seq   = (const int*)d_in[15];
    const int* items       = (const int*)d_in[16];
    const int* edge_index  = (const int*)d_in[17];
    const int* edge_type   = (const int*)d_in[18];
    // d_in[19] = node_no (identity gather, unused)
    const int* sedge_index = (const int*)d_in[20];
    const int* sedge_type  = (const int*)d_in[21];

    const int E  = in_sizes[18];   // 1,000,000
    const int SE = in_sizes[21];   //   200,000

    float* out_res  = (float*)d_out;                       // [1024][20]
    float* out_user = out_res + BATCH * NPRED;             // [1024][384]
    float* out_item = out_user + BATCH * TDIM;             // [1024][20][384]

    cudaFuncSetAttribute(dense_kernel,
                         cudaFuncAttributeMaxDynamicSharedMemorySize, DENSE_SMEM);

    const int dense_grid  = (NNODE + 63) / 64;             // 2344
    const int finish_grid = (N64 / 4 + 255) / 256;

    for (int l = 0; l < 6; ++l) {
        bool big = (l < 3);
        int  ll  = big ? l : l - 3;
        const float* B  = (big ? basis  : sbasis) + ll * 16384;
        const float* R  = (big ? root   : sroot)  + ll * 4096;
        const float* Bi = (big ? bias   : sbias)  + ll * 64;
        const float* C  = (big ? comp   : scomp)  + ll * 32;
        const int* srcs = big ? edge_index  : sedge_index;
        const int* tys  = big ? edge_type   : sedge_type;
        int Ecur        = big ? E : SE;
        const int* dsts = srcs + Ecur;

        dense_kernel<<<dense_grid, 256, DENSE_SMEM>>>(
            l == 0 ? node_emb : nullptr, l, B, R, Bi, C);
        edge_kernel<<<(Ecur + 15) / 16, 256>>>(srcs, dsts, tys, Ecur);
        finish_kernel<<<finish_grid, 256>>>(l * 64);
    }

    tail_a<<<BATCH, TDIM>>>(batch_users, batch_seq, out_user, out_item);
    tail_b<<<BATCH, TDIM>>>(WV, predict_w, predict_b, items, out_user, out_res);
}

// round 6
// speedup vs baseline: 1.4678x; 1.1154x over previous
#include <cuda_runtime.h>
#include <cstdint>
#include <cstddef>

// ---------------- problem constants ----------------
#define NNODE  150000
#define N64    (NNODE * 64)          // 9,600,000
#define TDIM   384                   // 2*LAYERS*DIM
#define BATCH  1024
#define SEQ    20
#define NPRED  20

// ---------------- scratch (device globals) ----------------
__device__ float g_xw[8ull * N64];           // xw_r = x @ W_r   [N][8][64]  (307 MB)
__device__ float g_agg[N64];                 // edge accumulator [N][64]
__device__ float g_cs[(size_t)NNODE * TDIM]; // concat of 6 states [N][384]
__device__ float g_ssum[BATCH * TDIM];       // per-batch sequence sums
__device__ float g_uv[BATCH * TDIM];         // user + ssum@WV

// ---------------- f32x2 helpers ----------------
__device__ __forceinline__ unsigned long long dup_f32x2(float v) {
    unsigned long long a;
    asm("mov.b64 %0, {%1, %1};" : "=l"(a) : "f"(v));
    return a;
}
__device__ __forceinline__ void ffma2(unsigned long long& acc,
                                      unsigned long long a, unsigned long long b) {
    asm("fma.rn.f32x2 %0, %1, %2, %0;" : "+l"(acc) : "l"(a), "l"(b));
}

// dense_xw smem layout
#define WS_ELEMS (64 * 256)          // basis0..3  [k][256]  (64 KB)
#define XS_LD    68
#define XS_ELEMS (64 * XS_LD)        // x transposed [k][row] (17.4 KB)
#define DENSE_SMEM ((WS_ELEMS + XS_ELEMS) * 4)   // 83,456 B  -> 2 blocks/SM

// =====================================================================
// dense_xw: 64-row tile, acc_b = x@basis_b (b=0..3), barrier-free loop.
// Epilogue: xw_r = sum_b comp[r,b]*acc_b -> g_xw[row][r][:] (streaming),
// and zero g_agg rows (disjoint per block) for the edge kernel.
// 2 blocks/SM (4 warps/SMSP) for latency hiding.
// =====================================================================
__global__ __launch_bounds__(256, 2) void dense_xw(
    const float* __restrict__ xin,   // nullptr -> g_cs slice
    int layer,
    const float* __restrict__ basis, // [4][64][64] layer slice
    const float* __restrict__ comp)  // [8][4] layer slice
{
    extern __shared__ float sm[];
    float* Ws = sm;                   // [64][256]
    float* Xs = sm + WS_ELEMS;        // [64][XS_LD]

    const float* xp;
    int xstride;
    if (xin != nullptr) { xp = xin; xstride = 64; }
    else               { xp = g_cs + (layer - 1) * 64; xstride = TDIM; }

    int t  = threadIdx.x;
    int tr = t >> 5;
    int tc = t & 31;
    int row0 = blockIdx.x * 64;

    // ---- preload basis: 4096 float4 ----
#pragma unroll
    for (int i = 0; i < 16; i++) {
        int idx = t + 256 * i;            // 0..4095
        int m  = idx >> 10;
        int rem = idx & 1023;
        int k  = rem >> 4;
        int e4 = rem & 15;
        float4 v = *reinterpret_cast<const float4*>(basis + m * 4096 + k * 64 + e4 * 4);
        *reinterpret_cast<float4*>(Ws + k * 256 + m * 64 + e4 * 4) = v;
    }
    // ---- preload x tile transposed: Xs[k][row] ----
#pragma unroll
    for (int i = 0; i < 4; i++) {
        int idx = t + 256 * i;            // 0..1023
        int row = idx >> 4;
        int kq  = (idx & 15) * 4;
        int gr  = row0 + row;
        float4 v = make_float4(0.f, 0.f, 0.f, 0.f);
        if (gr < NNODE)
            v = *reinterpret_cast<const float4*>(xp + (size_t)gr * xstride + kq);
        Xs[(kq + 0) * XS_LD + row] = v.x;
        Xs[(kq + 1) * XS_LD + row] = v.y;
        Xs[(kq + 2) * XS_LD + row] = v.z;
        Xs[(kq + 3) * XS_LD + row] = v.w;
    }
    __syncthreads();

    unsigned long long acc[8][4];
#pragma unroll
    for (int i = 0; i < 8; i++)
#pragma unroll
        for (int j = 0; j < 4; j++) acc[i][j] = 0ull;

#pragma unroll 4
    for (int k = 0; k < 64; ++k) {
        unsigned long long w[4];
#pragma unroll
        for (int jj = 0; jj < 4; jj++)
            w[jj] = *reinterpret_cast<const unsigned long long*>(
                        Ws + k * 256 + 64 * jj + 2 * tc);
        float4 xa = *reinterpret_cast<const float4*>(Xs + k * XS_LD + tr * 8);
        float4 xb = *reinterpret_cast<const float4*>(Xs + k * XS_LD + tr * 8 + 4);
        float xv[8] = {xa.x, xa.y, xa.z, xa.w, xb.x, xb.y, xb.z, xb.w};
#pragma unroll
        for (int i = 0; i < 8; i++) {
            unsigned long long a = dup_f32x2(xv[i]);
#pragma unroll
            for (int jj = 0; jj < 4; jj++) ffma2(acc[i][jj], a, w[jj]);
        }
    }

    // ---- epilogue: comp fold + streaming store; zero agg rows ----
    float4 cr[8];
#pragma unroll
    for (int r = 0; r < 8; r++)
        cr[r] = *reinterpret_cast<const float4*>(comp + r * 4);

#pragma unroll
    for (int i = 0; i < 8; i++) {
        int row = row0 + tr * 8 + i;
        if (row >= NNODE) break;
        float2 z = make_float2(0.f, 0.f);
        *reinterpret_cast<float2*>(g_agg + (size_t)row * 64 + 2 * tc) = z;
#pragma unroll
        for (int r = 0; r < 8; r++) {
            unsigned long long m = 0ull;
            ffma2(m, dup_f32x2(cr[r].x), acc[i][0]);
            ffma2(m, dup_f32x2(cr[r].y), acc[i][1]);
            ffma2(m, dup_f32x2(cr[r].z), acc[i][2]);
            ffma2(m, dup_f32x2(cr[r].w), acc[i][3]);
            __stcs(reinterpret_cast<float2*>(
                       g_xw + (size_t)row * 512 + r * 64 + 2 * tc),
                   *reinterpret_cast<float2*>(&m));
        }
    }
}

// =====================================================================
// Edge kernel: 16 lanes per edge; streaming gather of xw[src][et] (256B),
// atomicAdd(float4) into agg[dst] (L2-resident).
// =====================================================================
__global__ __launch_bounds__(256) void edge_kernel(
    const int* __restrict__ src,
    const int* __restrict__ dst,
    const int* __restrict__ et,
    int E)
{
    int e = blockIdx.x * 16 + (threadIdx.x >> 4);
    if (e >= E) return;
    int j = threadIdx.x & 15;

    int s  = __ldg(&src[e]);
    int d  = __ldg(&dst[e]);
    int ty = __ldg(&et[e]);

    float4 v = __ldcs(reinterpret_cast<const float4*>(
                   g_xw + (size_t)s * 512 + ty * 64 + j * 4));
    atomicAdd(reinterpret_cast<float4*>(g_agg + (size_t)d * 64 + j * 4), v);
}

// =====================================================================
// finish_root: cs[:, loff:loff+64] = tanh(agg + x@root + bias)
// 64-row tile; root in smem (16KB) + x transposed (17.4KB).
// =====================================================================
__global__ __launch_bounds__(256) void finish_root(
    const float* __restrict__ xin,   // same input state as dense_xw
    int layer,
    const float* __restrict__ root,  // [64][64]
    const float* __restrict__ bias,  // [64]
    int loff)
{
    __shared__ float Rs[64 * 64];
    __shared__ float Xs[64 * XS_LD];

    const float* xp;
    int xstride;
    if (xin != nullptr) { xp = xin; xstride = 64; }
    else               { xp = g_cs + (layer - 1) * 64; xstride = TDIM; }

    int t  = threadIdx.x;
    int tr = t >> 5;
    int tc = t & 31;
    int row0 = blockIdx.x * 64;

#pragma unroll
    for (int i = 0; i < 4; i++) {
        int idx = t + 256 * i;            // 0..1023 float4
        *reinterpret_cast<float4*>(Rs + idx * 4) =
            *reinterpret_cast<const float4*>(root + idx * 4);
    }
#pragma unroll
    for (int i = 0; i < 4; i++) {
        int idx = t + 256 * i;
        int row = idx >> 4;
        int kq  = (idx & 15) * 4;
        int gr  = row0 + row;
        float4 v = make_float4(0.f, 0.f, 0.f, 0.f);
        if (gr < NNODE)
            v = *reinterpret_cast<const float4*>(xp + (size_t)gr * xstride + kq);
        Xs[(kq + 0) * XS_LD + row] = v.x;
        Xs[(kq + 1) * XS_LD + row] = v.y;
        Xs[(kq + 2) * XS_LD + row] = v.z;
        Xs[(kq + 3) * XS_LD + row] = v.w;
    }
    __syncthreads();

    unsigned long long acc[8];
#pragma unroll
    for (int i = 0; i < 8; i++) acc[i] = 0ull;

#pragma unroll 4
    for (int k = 0; k < 64; ++k) {
        unsigned long long w = *reinterpret_cast<const unsigned long long*>(
                                   Rs + k * 64 + 2 * tc);
        float4 xa = *reinterpret_cast<const float4*>(Xs + k * XS_LD + tr * 8);
        float4 xb = *reinterpret_cast<const float4*>(Xs + k * XS_LD + tr * 8 + 4);
        float xv[8] = {xa.x, xa.y, xa.z, xa.w, xb.x, xb.y, xb.z, xb.w};
#pragma unroll
        for (int i = 0; i < 8; i++) ffma2(acc[i], dup_f32x2(xv[i]), w);
    }

    float b0 = bias[2 * tc];
    float b1 = bias[2 * tc + 1];
#pragma unroll
    for (int i = 0; i < 8; i++) {
        int row = row0 + tr * 8 + i;
        if (row >= NNODE) break;
        float2 a = *reinterpret_cast<const float2*>(g_agg + (size_t)row * 64 + 2 * tc);
        float2 v = *reinterpret_cast<float2*>(&acc[i]);
        v.x = tanhf(v.x + a.x + b0);
        v.y = tanhf(v.y + a.y + b1);
        *reinterpret_cast<float2*>(g_cs + (size_t)row * TDIM + loff + 2 * tc) = v;
    }
}

// =====================================================================
// Tail A: gather item_embs_conv + user_emb outputs, build sequence sums.
// =====================================================================
__global__ __launch_bounds__(TDIM) void tail_a(
    const int* __restrict__ users,
    const int* __restrict__ seqs,
    float* __restrict__ out_user,   // [BATCH][TDIM]
    float* __restrict__ out_item)   // [BATCH][SEQ][TDIM]
{
    int b = blockIdx.x;
    int t = threadIdx.x;
    float s = 0.f;
#pragma unroll
    for (int j = 0; j < SEQ; j++) {
        int node = __ldg(&seqs[b * SEQ + j]);
        float v  = __ldg(&g_cs[(size_t)node * TDIM + t]);
        out_item[((size_t)b * SEQ + j) * TDIM + t] = v;
        s += v;
    }
    g_ssum[b * TDIM + t] = s;
    int u = __ldg(&users[b]);
    out_user[b * TDIM + t] = __ldg(&g_cs[(size_t)u * TDIM + t]);
}

// =====================================================================
// tb_uv: uv = user_emb + ssum @ WV.  8 batches per block to amortize WV.
// (attention collapses: softmax over query axis => column sums == 1)
// =====================================================================
__global__ __launch_bounds__(TDIM) void tb_uv(
    const float* __restrict__ WV,        // [TDIM][TDIM]
    const float* __restrict__ user_emb)  // [BATCH][TDIM]
{
    __shared__ float ss[8 * TDIM];
    int b0 = blockIdx.x * 8;
    int t  = threadIdx.x;

#pragma unroll
    for (int i = 0; i < 8; i++)
        ss[i * TDIM + t] = g_ssum[(b0 + i) * TDIM + t];
    __syncthreads();

    float acc[8];
#pragma unroll
    for (int i = 0; i < 8; i++) acc[i] = 0.f;

#pragma unroll 4
    for (int k = 0; k < TDIM; ++k) {
        float w = __ldg(&WV[k * TDIM + t]);
#pragma unroll
        for (int i = 0; i < 8; i++) acc[i] = fmaf(ss[i * TDIM + k], w, acc[i]);
    }
#pragma unroll
    for (int i = 0; i < 8; i++)
        g_uv[(b0 + i) * TDIM + t] = acc[i] + user_emb[(b0 + i) * TDIM + t];
}

// =====================================================================
// tb_res: res[b,k] = pe_w[item]·uv[b] + pe_b[item]
// =====================================================================
__global__ __launch_bounds__(TDIM) void tb_res(
    const float* __restrict__ predict_w, // [NITEM][TDIM]
    const float* __restrict__ predict_b, // [NITEM]
    const int*   __restrict__ items,     // [BATCH][NPRED]
    float* __restrict__ res)             // [BATCH][NPRED]
{
    __shared__ float uv[TDIM];
    int b = blockIdx.x;
    int t = threadIdx.x;
    uv[t] = g_uv[b * TDIM + t];
    __syncthreads();

    int w    = t >> 5;
    int lane = t & 31;
    for (int k = w; k < NPRED; k += TDIM / 32) {
        int it = __ldg(&items[b * NPRED + k]);
        const float* pw = predict_w + (size_t)it * TDIM;
        float s = 0.f;
#pragma unroll
        for (int c = lane; c < TDIM; c += 32) s += __ldg(&pw[c]) * uv[c];
#pragma unroll
        for (int off = 16; off > 0; off >>= 1)
            s += __shfl_down_sync(0xffffffffu, s, off);
        if (lane == 0)
            res[b * NPRED + k] = s + __ldg(&predict_b[it]);
    }
}

// =====================================================================
// Launch
// =====================================================================
extern "C" void kernel_launch(void* const* d_in, const int* in_sizes, int n_in,
                              void* d_out, int out_size)
{
    const float* node_emb  = (const float*)d_in[0];
    const float* predict_w = (const float*)d_in[1];
    const float* predict_b = (const float*)d_in[2];
    const float* basis     = (const float*)d_in[3];
    const float* comp      = (const float*)d_in[4];
    const float* root      = (const float*)d_in[5];
    const float* bias      = (const float*)d_in[6];
    const float* sbasis    = (const float*)d_in[7];
    const float* scomp     = (const float*)d_in[8];
    const float* sroot     = (const float*)d_in[9];
    const float* sbias     = (const float*)d_in[10];
    // d_in[11] = WQ, d_in[12] = WK : provably unused (softmax over query axis)
    const float* WV        = (const float*)d_in[13];
    const int* batch_users = (const int*)d_in[14];
    const int* batch_seq   = (const int*)d_in[15];
    const int* items       = (const int*)d_in[16];
    const int* edge_index  = (const int*)d_in[17];
    const int* edge_type   = (const int*)d_in[18];
    // d_in[19] = node_no (identity gather, unused)
    const int* sedge_index = (const int*)d_in[20];
    const int* sedge_type  = (const int*)d_in[21];

    const int E  = in_sizes[18];   // 1,000,000
    const int SE = in_sizes[21];   //   200,000

    float* out_res  = (float*)d_out;                       // [1024][20]
    float* out_user = out_res + BATCH * NPRED;             // [1024][384]
    float* out_item = out_user + BATCH * TDIM;             // [1024][20][384]

    cudaFuncSetAttribute(dense_xw,
                         cudaFuncAttributeMaxDynamicSharedMemorySize, DENSE_SMEM);

    const int dense_grid = (NNODE + 63) / 64;              // 2344

    for (int l = 0; l < 6; ++l) {
        bool big = (l < 3);
        int  ll  = big ? l : l - 3;
        const float* B  = (big ? basis  : sbasis) + ll * 16384;
        const float* R  = (big ? root   : sroot)  + ll * 4096;
        const float* Bi = (big ? bias   : sbias)  + ll * 64;
        const float* C  = (big ? comp   : scomp)  + ll * 32;
        const int* srcs = big ? edge_index  : sedge_index;
        const int* tys  = big ? edge_type   : sedge_type;
        int Ecur        = big ? E : SE;
        const int* dsts = srcs + Ecur;
        const float* xi = (l == 0) ? node_emb : nullptr;

        dense_xw<<<dense_grid, 256, DENSE_SMEM>>>(xi, l, B, C);
        edge_kernel<<<(Ecur + 15) / 16, 256>>>(srcs, dsts, tys, Ecur);
        finish_root<<<dense_grid, 256>>>(xi, l, R, Bi, l * 64);
    }

    tail_a<<<BATCH, TDIM>>>(batch_users, batch_seq, out_user, out_item);
    tb_uv<<<BATCH / 8, TDIM>>>(WV, out_user);
    tb_res<<<BATCH, TDIM>>>(predict_w, predict_b, items, out_res);
}

// round 11
// speedup vs baseline: 1.7475x; 1.1906x over previous
#include <cuda_runtime.h>
#include <cuda_bf16.h>
#include <cstdint>
#include <cstddef>

// ---------------- problem constants ----------------
#define NNODE  150000
#define N64    (NNODE * 64)          // 9,600,000
#define TDIM   384
#define BATCH  1024
#define SEQ    20
#define NPRED  20

// ---------------- scratch (device globals) ----------------
__device__ float g_xw[8ull * N64];           // xw_r = x @ W_r   [N][8][64]  (307 MB)
__device__ float g_agg[N64];                 // accumulator [N][64]
__device__ float g_cs[(size_t)NNODE * TDIM]; // concat of 6 states [N][384]
__device__ float g_ssum[BATCH * TDIM];
__device__ float g_uv[BATCH * TDIM];
// bf16 W image, [n][k] stride-72 halfs: [hi 23040][lo 23040]
__device__ unsigned short g_wimg[2 * 320 * 72];

// ---------------- helpers ----------------
__device__ __forceinline__ unsigned long long dup_f32x2(float v) {
    unsigned long long a;
    asm("mov.b64 %0, {%1, %1};" : "=l"(a) : "f"(v));
    return a;
}
__device__ __forceinline__ unsigned long long pack_f32x2(float x, float y) {
    unsigned long long a;
    asm("mov.b64 %0, {%1, %2};" : "=l"(a) : "f"(x), "f"(y));
    return a;
}
__device__ __forceinline__ void ffma2(unsigned long long& acc,
                                      unsigned long long a, unsigned long long b) {
    asm("fma.rn.f32x2 %0, %1, %2, %0;" : "+l"(acc) : "l"(a), "l"(b));
}

// mma.sync m16n8k16 bf16 (baseline PTX, works on compute_103)
#define MMA_BF16(d, a, b0_, b1_) \
    asm volatile("mma.sync.aligned.m16n8k16.row.col.f32.bf16.bf16.f32 " \
        "{%0,%1,%2,%3}, {%4,%5,%6,%7}, {%8,%9}, {%0,%1,%2,%3};" \
        : "+f"((d)[0]), "+f"((d)[1]), "+f"((d)[2]), "+f"((d)[3]) \
        : "r"((a)[0]), "r"((a)[1]), "r"((a)[2]), "r"((a)[3]), \
          "r"(b0_), "r"(b1_))

// smem byte offsets for tc_dense (stride 144B per row everywhere)
#define SM_XHI   0
#define SM_XLO   (256 * 144)             // 36864
#define SM_WHI   (2 * 256 * 144)         // 73728
#define SM_WLO   (SM_WHI + 320 * 144)    // 119808
#define SM_COMP  (SM_WLO + 320 * 144)    // 165888
#define SM_BIASO (SM_COMP + 128)         // 166016
#define TC_SMEM  (SM_BIASO + 256)        // 166272

// =====================================================================
// w_prep: W = [basis0..3 | root] as bf16 hi/lo, layout [n][k], stride 72
// n<256: basis[n>>6][k][n&63];  n>=256: root[k][n-256]
// =====================================================================
__global__ __launch_bounds__(256) void w_prep(
    const float* __restrict__ basis, const float* __restrict__ root)
{
    int idx = blockIdx.x * 256 + threadIdx.x;      // 0..20479
    if (idx >= 320 * 64) return;
    int n = idx >> 6;
    int k = idx & 63;
    float v = (n < 256) ? basis[(n >> 6) * 4096 + k * 64 + (n & 63)]
                        : root[k * 64 + (n - 256)];
    __nv_bfloat16 h = __float2bfloat16(v);
    __nv_bfloat16 l = __float2bfloat16(v - __bfloat162float(h));
    g_wimg[n * 72 + k]                 = __bfloat16_as_ushort(h);
    g_wimg[320 * 72 + n * 72 + k]      = __bfloat16_as_ushort(l);
}

// =====================================================================
// tc_dense: 256-row tile, 512 threads (16 warps x 16 rows).
// y = x @ [basis0..3 | root] via mma.sync bf16 3-term split, fp32 accum.
// Epilogue: xw_r = sum_b comp[r,b]*y_b -> g_xw;  g_agg = y_root + bias.
// =====================================================================
__global__ __launch_bounds__(512, 1) void tc_dense(
    const float* __restrict__ xin,   // nullptr -> g_cs slice
    int layer,
    const float* __restrict__ comp,  // [8][4]
    const float* __restrict__ bias)  // [64]
{
    extern __shared__ char sm[];
    int tid = threadIdx.x;

    // ---- copy W image (92160 B = 5760 uint4) ----
    {
        const uint4* wi = reinterpret_cast<const uint4*>(g_wimg);
#pragma unroll
        for (int i = 0; i < 12; i++) {
            int idx = tid + 512 * i;
            if (idx < 5760)
                *reinterpret_cast<uint4*>(sm + SM_WHI + idx * 16) = wi[idx];
        }
    }
    if (tid < 32) reinterpret_cast<float*>(sm + SM_COMP)[tid] = comp[tid];
    if (tid >= 64 && tid < 128)
        reinterpret_cast<float*>(sm + SM_BIASO)[tid - 64] = bias[tid - 64];

    // ---- stage x tile as bf16 hi/lo, stride 72 halfs ----
    const float* xp;
    int xstride;
    if (xin != nullptr) { xp = xin; xstride = 64; }
    else               { xp = g_cs + (layer - 1) * 64; xstride = TDIM; }

    {
        int row  = tid >> 1;             // 0..255
        int half = tid & 1;              // 32-col halves
        int grow = blockIdx.x * 256 + row;
        const float* xr = xp + (size_t)grow * xstride + half * 32;
        char* xh = sm + SM_XHI + row * 144 + half * 64;
        char* xl = sm + SM_XLO + row * 144 + half * 64;
#pragma unroll
        for (int q = 0; q < 8; q++) {
            float4 v = make_float4(0.f, 0.f, 0.f, 0.f);
            if (grow < NNODE) v = *reinterpret_cast<const float4*>(xr + q * 4);
            __nv_bfloat16 h0 = __float2bfloat16(v.x), h1 = __float2bfloat16(v.y);
            __nv_bfloat16 h2 = __float2bfloat16(v.z), h3 = __float2bfloat16(v.w);
            uint2 hp;
            hp.x = (uint32_t)__bfloat16_as_ushort(h0) | ((uint32_t)__bfloat16_as_ushort(h1) << 16);
            hp.y = (uint32_t)__bfloat16_as_ushort(h2) | ((uint32_t)__bfloat16_as_ushort(h3) << 16);
            __nv_bfloat16 l0 = __float2bfloat16(v.x - __bfloat162float(h0));
            __nv_bfloat16 l1 = __float2bfloat16(v.y - __bfloat162float(h1));
            __nv_bfloat16 l2 = __float2bfloat16(v.z - __bfloat162float(h2));
            __nv_bfloat16 l3 = __float2bfloat16(v.w - __bfloat162float(h3));
            uint2 lp;
            lp.x = (uint32_t)__bfloat16_as_ushort(l0) | ((uint32_t)__bfloat16_as_ushort(l1) << 16);
            lp.y = (uint32_t)__bfloat16_as_ushort(l2) | ((uint32_t)__bfloat16_as_ushort(l3) << 16);
            *reinterpret_cast<uint2*>(xh + q * 8) = hp;
            *reinterpret_cast<uint2*>(xl + q * 8) = lp;
        }
    }
    __syncthreads();

    // ---- per-warp MMA: 16 rows x 320 cols ----
    int lane = tid & 31, wid = tid >> 5;
    int g = lane >> 2, j = lane & 3;
    int lr = wid * 16 + g;               // local row for d0/d1 (d2/d3: +8)
    int grow0 = blockIdx.x * 256 + lr;

    // A fragments (hi and lo), per PTX m16n8k16 mapping
    uint32_t Ah[4][4], Al[4][4];
#pragma unroll
    for (int ks = 0; ks < 4; ks++) {
        int c2 = (ks * 16 + 2 * j) * 2;  // byte offset of col
        Ah[ks][0] = *reinterpret_cast<const uint32_t*>(sm + SM_XHI + lr * 144 + c2);
        Ah[ks][1] = *reinterpret_cast<const uint32_t*>(sm + SM_XHI + (lr + 8) * 144 + c2);
        Ah[ks][2] = *reinterpret_cast<const uint32_t*>(sm + SM_XHI + lr * 144 + c2 + 16);
        Ah[ks][3] = *reinterpret_cast<const uint32_t*>(sm + SM_XHI + (lr + 8) * 144 + c2 + 16);
        Al[ks][0] = *reinterpret_cast<const uint32_t*>(sm + SM_XLO + lr * 144 + c2);
        Al[ks][1] = *reinterpret_cast<const uint32_t*>(sm + SM_XLO + (lr + 8) * 144 + c2);
        Al[ks][2] = *reinterpret_cast<const uint32_t*>(sm + SM_XLO + lr * 144 + c2 + 16);
        Al[ks][3] = *reinterpret_cast<const uint32_t*>(sm + SM_XLO + (lr + 8) * 144 + c2 + 16);
    }

    // ---- basis columns: 8 e-groups x 4 basis-tiles ----
#pragma unroll
    for (int eg = 0; eg < 8; eg++) {
        float acc[4][4];
#pragma unroll
        for (int bt = 0; bt < 4; bt++)
#pragma unroll
            for (int q = 0; q < 4; q++) acc[bt][q] = 0.f;

#pragma unroll
        for (int ks = 0; ks < 4; ks++) {
            int kb2 = (ks * 16 + 2 * j) * 2;
            uint32_t Bh[4][2], Bl[4][2];
#pragma unroll
            for (int bt = 0; bt < 4; bt++) {
                int n = bt * 64 + eg * 8 + g;
                const char* wh = sm + SM_WHI + n * 144 + kb2;
                const char* wl = sm + SM_WLO + n * 144 + kb2;
                Bh[bt][0] = *reinterpret_cast<const uint32_t*>(wh);
                Bh[bt][1] = *reinterpret_cast<const uint32_t*>(wh + 16);
                Bl[bt][0] = *reinterpret_cast<const uint32_t*>(wl);
                Bl[bt][1] = *reinterpret_cast<const uint32_t*>(wl + 16);
            }
            // interleave b-tiles so acc dependency chains are 4 apart
#pragma unroll
            for (int bt = 0; bt < 4; bt++) MMA_BF16(acc[bt], Ah[ks], Bh[bt][0], Bh[bt][1]);
#pragma unroll
            for (int bt = 0; bt < 4; bt++) MMA_BF16(acc[bt], Ah[ks], Bl[bt][0], Bl[bt][1]);
#pragma unroll
            for (int bt = 0; bt < 4; bt++) MMA_BF16(acc[bt], Al[ks], Bh[bt][0], Bh[bt][1]);
        }

        // comp fold (thread-local) + store
        unsigned long long p0[4], p1[4];
#pragma unroll
        for (int bt = 0; bt < 4; bt++) {
            p0[bt] = pack_f32x2(acc[bt][0], acc[bt][1]);   // row lr
            p1[bt] = pack_f32x2(acc[bt][2], acc[bt][3]);   // row lr+8
        }
        int e = eg * 8 + 2 * j;
#pragma unroll
        for (int rel = 0; rel < 8; rel++) {
            float4 c4 = *reinterpret_cast<const float4*>(sm + SM_COMP + rel * 16);
            unsigned long long s0 = 0ull, s1 = 0ull;
            ffma2(s0, dup_f32x2(c4.x), p0[0]); ffma2(s1, dup_f32x2(c4.x), p1[0]);
            ffma2(s0, dup_f32x2(c4.y), p0[1]); ffma2(s1, dup_f32x2(c4.y), p1[1]);
            ffma2(s0, dup_f32x2(c4.z), p0[2]); ffma2(s1, dup_f32x2(c4.z), p1[2]);
            ffma2(s0, dup_f32x2(c4.w), p0[3]); ffma2(s1, dup_f32x2(c4.w), p1[3]);
            if (grow0 < NNODE)
                __stcs(reinterpret_cast<float2*>(
                           g_xw + (size_t)grow0 * 512 + rel * 64 + e),
                       *reinterpret_cast<float2*>(&s0));
            if (grow0 + 8 < NNODE)
                __stcs(reinterpret_cast<float2*>(
                           g_xw + (size_t)(grow0 + 8) * 512 + rel * 64 + e),
                       *reinterpret_cast<float2*>(&s1));
        }
    }

    // ---- root columns -> g_agg (+bias) ----
    const float* sb = reinterpret_cast<const float*>(sm + SM_BIASO);
#pragma unroll
    for (int nt = 0; nt < 8; nt++) {
        float acc[4] = {0.f, 0.f, 0.f, 0.f};
#pragma unroll
        for (int ks = 0; ks < 4; ks++) {
            int kb2 = (ks * 16 + 2 * j) * 2;
            int n = 256 + nt * 8 + g;
            const char* wh = sm + SM_WHI + n * 144 + kb2;
            const char* wl = sm + SM_WLO + n * 144 + kb2;
            uint32_t bh0 = *reinterpret_cast<const uint32_t*>(wh);
            uint32_t bh1 = *reinterpret_cast<const uint32_t*>(wh + 16);
            uint32_t bl0 = *reinterpret_cast<const uint32_t*>(wl);
            uint32_t bl1 = *reinterpret_cast<const uint32_t*>(wl + 16);
            MMA_BF16(acc, Ah[ks], bh0, bh1);
            MMA_BF16(acc, Ah[ks], bl0, bl1);
            MMA_BF16(acc, Al[ks], bh0, bh1);
        }
        int e = nt * 8 + 2 * j;
        float b0 = sb[e], b1 = sb[e + 1];
        if (grow0 < NNODE) {
            float2 v = make_float2(acc[0] + b0, acc[1] + b1);
            *reinterpret_cast<float2*>(g_agg + (size_t)grow0 * 64 + e) = v;
        }
        if (grow0 + 8 < NNODE) {
            float2 v = make_float2(acc[2] + b0, acc[3] + b1);
            *reinterpret_cast<float2*>(g_agg + (size_t)(grow0 + 8) * 64 + e) = v;
        }
    }
}

// =====================================================================
// Edge kernel: 16 lanes per edge; streaming gather of xw[src][et] (256B),
// atomicAdd(float4) into agg[dst] (L2-resident).
// =====================================================================
__global__ __launch_bounds__(256) void edge_kernel(
    const int* __restrict__ src,
    const int* __restrict__ dst,
    const int* __restrict__ et,
    int E)
{
    int e = blockIdx.x * 16 + (threadIdx.x >> 4);
    if (e >= E) return;
    int j = threadIdx.x & 15;

    int s  = __ldg(&src[e]);
    int d  = __ldg(&dst[e]);
    int ty = __ldg(&et[e]);

    float4 v = __ldcs(reinterpret_cast<const float4*>(
                   g_xw + (size_t)s * 512 + ty * 64 + j * 4));
    atomicAdd(reinterpret_cast<float4*>(g_agg + (size_t)d * 64 + j * 4), v);
}

// =====================================================================
// finish_tanh: cs[:, loff:loff+64] = tanh(agg)
// =====================================================================
__global__ __launch_bounds__(256) void finish_tanh(int loff)
{
    int idx4 = blockIdx.x * 256 + threadIdx.x;
    if (idx4 >= N64 / 4) return;
    float4 v = *reinterpret_cast<const float4*>(g_agg + (size_t)idx4 * 4);
    v.x = tanhf(v.x); v.y = tanhf(v.y); v.z = tanhf(v.z); v.w = tanhf(v.w);
    int n  = idx4 >> 4;
    int jj = (idx4 & 15) * 4;
    *reinterpret_cast<float4*>(g_cs + (size_t)n * TDIM + loff + jj) = v;
}

// =====================================================================
// Tail A: gather item_embs_conv + user_emb outputs, build sequence sums.
// =====================================================================
__global__ __launch_bounds__(TDIM) void tail_a(
    const int* __restrict__ users,
    const int* __restrict__ seqs,
    float* __restrict__ out_user,
    float* __restrict__ out_item)
{
    int b = blockIdx.x;
    int t = threadIdx.x;
    float s = 0.f;
#pragma unroll
    for (int j = 0; j < SEQ; j++) {
        int node = __ldg(&seqs[b * SEQ + j]);
        float v  = __ldg(&g_cs[(size_t)node * TDIM + t]);
        out_item[((size_t)b * SEQ + j) * TDIM + t] = v;
        s += v;
    }
    g_ssum[b * TDIM + t] = s;
    int u = __ldg(&users[b]);
    out_user[b * TDIM + t] = __ldg(&g_cs[(size_t)u * TDIM + t]);
}

// =====================================================================
// tb_uv: uv = user_emb + ssum @ WV.  8 batches per block.
// (attention collapses: softmax over query axis => column sums == 1)
// =====================================================================
__global__ __launch_bounds__(TDIM) void tb_uv(
    const float* __restrict__ WV,
    const float* __restrict__ user_emb)
{
    __shared__ float ss[8 * TDIM];
    int b0 = blockIdx.x * 8;
    int t  = threadIdx.x;

#pragma unroll
    for (int i = 0; i < 8; i++)
        ss[i * TDIM + t] = g_ssum[(b0 + i) * TDIM + t];
    __syncthreads();

    float acc[8];
#pragma unroll
    for (int i = 0; i < 8; i++) acc[i] = 0.f;

#pragma unroll 4
    for (int k = 0; k < TDIM; ++k) {
        float w = __ldg(&WV[k * TDIM + t]);
#pragma unroll
        for (int i = 0; i < 8; i++) acc[i] = fmaf(ss[i * TDIM + k], w, acc[i]);
    }
#pragma unroll
    for (int i = 0; i < 8; i++)
        g_uv[(b0 + i) * TDIM + t] = acc[i] + user_emb[(b0 + i) * TDIM + t];
}

// =====================================================================
// tb_res: res[b,k] = pe_w[item]·uv[b] + pe_b[item]
// =====================================================================
__global__ __launch_bounds__(TDIM) void tb_res(
    const float* __restrict__ predict_w,
    const float* __restrict__ predict_b,
    const int*   __restrict__ items,
    float* __restrict__ res)
{
    __shared__ float uv[TDIM];
    int b = blockIdx.x;
    int t = threadIdx.x;
    uv[t] = g_uv[b * TDIM + t];
    __syncthreads();

    int w    = t >> 5;
    int lane = t & 31;
    for (int k = w; k < NPRED; k += TDIM / 32) {
        int it = __ldg(&items[b * NPRED + k]);
        const float* pw = predict_w + (size_t)it * TDIM;
        float s = 0.f;
#pragma unroll
        for (int c = lane; c < TDIM; c += 32) s += __ldg(&pw[c]) * uv[c];
#pragma unroll
        for (int off = 16; off > 0; off >>= 1)
            s += __shfl_down_sync(0xffffffffu, s, off);
        if (lane == 0)
            res[b * NPRED + k] = s + __ldg(&predict_b[it]);
    }
}

// =====================================================================
// Launch
// =====================================================================
extern "C" void kernel_launch(void* const* d_in, const int* in_sizes, int n_in,
                              void* d_out, int out_size)
{
    const float* node_emb  = (const float*)d_in[0];
    const float* predict_w = (const float*)d_in[1];
    const float* predict_b = (const float*)d_in[2];
    const float* basis     = (const float*)d_in[3];
    const float* comp      = (const float*)d_in[4];
    const float* root      = (const float*)d_in[5];
    const float* bias      = (const float*)d_in[6];
    const float* sbasis    = (const float*)d_in[7];
    const float* scomp     = (const float*)d_in[8];
    const float* sroot     = (const float*)d_in[9];
    const float* sbias     = (const float*)d_in[10];
    // d_in[11] = WQ, d_in[12] = WK : provably unused (softmax over query axis)
    const float* WV        = (const float*)d_in[13];
    const int* batch_users = (const int*)d_in[14];
    const int* batch_seq   = (const int*)d_in[15];
    const int* items       = (const int*)d_in[16];
    const int* edge_index  = (const int*)d_in[17];
    const int* edge_type   = (const int*)d_in[18];
    // d_in[19] = node_no (identity gather, unused)
    const int* sedge_index = (const int*)d_in[20];
    const int* sedge_type  = (const int*)d_in[21];

    const int E  = in_sizes[18];   // 1,000,000
    const int SE = in_sizes[21];   //   200,000

    float* out_res  = (float*)d_out;                       // [1024][20]
    float* out_user = out_res + BATCH * NPRED;             // [1024][384]
    float* out_item = out_user + BATCH * TDIM;             // [1024][20][384]

    cudaFuncSetAttribute(tc_dense,
                         cudaFuncAttributeMaxDynamicSharedMemorySize, TC_SMEM);

    const int tc_grid     = (NNODE + 255) / 256;           // 586
    const int finish_grid = (N64 / 4 + 255) / 256;

    for (int l = 0; l < 6; ++l) {
        bool big = (l < 3);
        int  ll  = big ? l : l - 3;
        const float* B  = (big ? basis  : sbasis) + ll * 16384;
        const float* R  = (big ? root   : sroot)  + ll * 4096;
        const float* Bi = (big ? bias   : sbias)  + ll * 64;
        const float* C  = (big ? comp   : scomp)  + ll * 32;
        const int* srcs = big ? edge_index  : sedge_index;
        const int* tys  = big ? edge_type   : sedge_type;
        int Ecur        = big ? E : SE;
        const int* dsts = srcs + Ecur;
        const float* xi = (l == 0) ? node_emb : nullptr;

        w_prep<<<80, 256>>>(B, R);
        tc_dense<<<tc_grid, 512, TC_SMEM>>>(xi, l, C, Bi);
        edge_kernel<<<(Ecur + 15) / 16, 256>>>(srcs, dsts, tys, Ecur);
        finish_tanh<<<finish_grid, 256>>>(l * 64);
    }

    tail_a<<<BATCH, TDIM>>>(batch_users, batch_seq, out_user, out_item);
    tb_uv<<<BATCH / 8, TDIM>>>(WV, out_user);
    tb_res<<<BATCH, TDIM>>>(predict_w, predict_b, items, out_res);
}

// round 15
// speedup vs baseline: 1.8622x; 1.0656x over previous
#include <cuda_runtime.h>
#include <cuda_bf16.h>
#include <cstdint>
#include <cstddef>

// ---------------- problem constants ----------------
#define NNODE  150000
#define N64    (NNODE * 64)          // 9,600,000
#define TDIM   384
#define BATCH  1024
#define SEQ    20
#define NPRED  20
#define EMAX   1000000
#define SEMAX  200000
#define NBINS  (2 * NNODE + 2)       // big rowptr [0..N], small [N+1..2N+1]
#define NSCANB ((NBINS + 1023) / 1024)

// ---------------- scratch (device globals) ----------------
__device__ float g_xw[8ull * N64];           // xw_r = x @ W_r   [N][8][64]  (307 MB)
__device__ float g_agg[N64];                 // root + bias      [N][64]
__device__ float g_cs[(size_t)NNODE * TDIM]; // concat of 6 states [N][384]
__device__ float g_ssum[BATCH * TDIM];
__device__ float g_uv[BATCH * TDIM];
// all 6 layers' bf16 W images: per layer [hi 320x72][lo 320x72] halfs
__device__ unsigned short g_wimg_all[6][2 * 320 * 72];
// CSR structures (both graphs share one packed edge array)
__device__ int g_rowptr[NBINS];
__device__ int g_cursor[NBINS];
__device__ int g_blocksum[NSCANB + 1];
__device__ unsigned int g_epack[EMAX + SEMAX];

// ---------------- helpers ----------------
__device__ __forceinline__ unsigned long long dup_f32x2(float v) {
    unsigned long long a;
    asm("mov.b64 %0, {%1, %1};" : "=l"(a) : "f"(v));
    return a;
}
__device__ __forceinline__ unsigned long long pack_f32x2(float x, float y) {
    unsigned long long a;
    asm("mov.b64 %0, {%1, %2};" : "=l"(a) : "f"(x), "f"(y));
    return a;
}
__device__ __forceinline__ void ffma2(unsigned long long& acc,
                                      unsigned long long a, unsigned long long b) {
    asm("fma.rn.f32x2 %0, %1, %2, %0;" : "+l"(acc) : "l"(a), "l"(b));
}

// mma.sync m16n8k16 bf16 (baseline PTX, works on compute_103)
#define MMA_BF16(d, a, b0_, b1_) \
    asm volatile("mma.sync.aligned.m16n8k16.row.col.f32.bf16.bf16.f32 " \
        "{%0,%1,%2,%3}, {%4,%5,%6,%7}, {%8,%9}, {%0,%1,%2,%3};" \
        : "+f"((d)[0]), "+f"((d)[1]), "+f"((d)[2]), "+f"((d)[3]) \
        : "r"((a)[0]), "r"((a)[1]), "r"((a)[2]), "r"((a)[3]), \
          "r"(b0_), "r"(b1_))

// smem byte offsets for tc_dense (stride 144B per row everywhere)
#define SM_XHI   0
#define SM_XLO   (256 * 144)             // 36864
#define SM_WHI   (2 * 256 * 144)         // 73728
#define SM_WLO   (SM_WHI + 320 * 144)    // 119808
#define SM_COMP  (SM_WLO + 320 * 144)    // 165888
#define SM_BIASO (SM_COMP + 128)         // 166016
#define TC_SMEM  (SM_BIASO + 256)        // 166272

// =====================================================================
// w_prep_all: bake all 6 layers' W = [basis0..3 | root] bf16 hi/lo
// images, layout [n][k] stride 72 halfs.
// =====================================================================
__global__ __launch_bounds__(256) void w_prep_all(
    const float* __restrict__ basis, const float* __restrict__ root,
    const float* __restrict__ sbasis, const float* __restrict__ sroot)
{
    int idx = blockIdx.x * 256 + threadIdx.x;      // 0..122879
    if (idx >= 6 * 320 * 64) return;
    int l   = idx / (320 * 64);
    int rem = idx - l * (320 * 64);
    int n = rem >> 6;
    int k = rem & 63;
    const float* B = (l < 3) ? basis + l * 16384 : sbasis + (l - 3) * 16384;
    const float* R = (l < 3) ? root + l * 4096  : sroot + (l - 3) * 4096;
    float v = (n < 256) ? B[(n >> 6) * 4096 + k * 64 + (n & 63)]
                        : R[k * 64 + (n - 256)];
    __nv_bfloat16 h = __float2bfloat16(v);
    __nv_bfloat16 lo = __float2bfloat16(v - __bfloat162float(h));
    g_wimg_all[l][n * 72 + k]            = __bfloat16_as_ushort(h);
    g_wimg_all[l][320 * 72 + n * 72 + k] = __bfloat16_as_ushort(lo);
}

// =====================================================================
// CSR build: zero -> hist -> scan(3 phase) -> scatter
// bins: big dst d at [d], small dst d at [NNODE+1+d].
// =====================================================================
__global__ __launch_bounds__(1024) void csr_zero()
{
    int i = blockIdx.x * 1024 + threadIdx.x;
    if (i < NBINS) g_rowptr[i] = 0;
}

__global__ __launch_bounds__(256) void csr_hist(
    const int* __restrict__ dstB, const int* __restrict__ dstS, int E, int SE)
{
    int i = blockIdx.x * 256 + threadIdx.x;
    if (i < E) {
        atomicAdd(&g_rowptr[__ldg(&dstB[i])], 1);
    } else if (i < E + SE) {
        atomicAdd(&g_rowptr[NNODE + 1 + __ldg(&dstS[i - E])], 1);
    }
}

__global__ __launch_bounds__(1024) void csr_scan1()
{
    __shared__ int s[1024];
    int tid = threadIdx.x;
    int gid = blockIdx.x * 1024 + tid;
    int v = (gid < NBINS) ? g_rowptr[gid] : 0;
    s[tid] = v;
    __syncthreads();
#pragma unroll
    for (int off = 1; off < 1024; off <<= 1) {
        int t = (tid >= off) ? s[tid - off] : 0;
        __syncthreads();
        s[tid] += t;
        __syncthreads();
    }
    if (gid < NBINS) g_rowptr[gid] = s[tid] - v;     // exclusive within block
    if (tid == 1023) g_blocksum[blockIdx.x] = s[1023];
}

__global__ void csr_scan2()
{
    if (threadIdx.x == 0 && blockIdx.x == 0) {
        int run = 0;
        for (int b = 0; b < NSCANB; b++) {
            int t = g_blocksum[b];
            g_blocksum[b] = run;
            run += t;
        }
    }
}

__global__ __launch_bounds__(1024) void csr_scan3()
{
    int gid = blockIdx.x * 1024 + threadIdx.x;
    if (gid < NBINS) {
        int v = g_rowptr[gid] + g_blocksum[gid >> 10];
        g_rowptr[gid] = v;
        g_cursor[gid] = v;
    }
}

__global__ __launch_bounds__(256) void csr_scatter(
    const int* __restrict__ srcB, const int* __restrict__ dstB,
    const int* __restrict__ etB,
    const int* __restrict__ srcS, const int* __restrict__ dstS,
    const int* __restrict__ etS, int E, int SE)
{
    int i = blockIdx.x * 256 + threadIdx.x;
    if (i < E) {
        int d = __ldg(&dstB[i]);
        unsigned pk = (unsigned)__ldg(&srcB[i]) | ((unsigned)__ldg(&etB[i]) << 20);
        int pos = atomicAdd(&g_cursor[d], 1);
        g_epack[pos] = pk;
    } else if (i < E + SE) {
        int k = i - E;
        int d = __ldg(&dstS[k]);
        unsigned pk = (unsigned)__ldg(&srcS[k]) | ((unsigned)__ldg(&etS[k]) << 20);
        int pos = atomicAdd(&g_cursor[NNODE + 1 + d], 1);
        g_epack[pos] = pk;
    }
}

// =====================================================================
// tc_dense: 256-row tile, 512 threads (16 warps x 16 rows).
// y = x @ [basis0..3 | root] via mma.sync bf16 3-term split, fp32 accum.
// Epilogue: xw_r = sum_b comp[r,b]*y_b -> g_xw;  g_agg = y_root + bias.
// =====================================================================
__global__ __launch_bounds__(512, 1) void tc_dense(
    const float* __restrict__ xin,   // nullptr -> g_cs slice
    int layer,
    const float* __restrict__ comp,  // [8][4]
    const float* __restrict__ bias)  // [64]
{
    extern __shared__ char sm[];
    int tid = threadIdx.x;

    // ---- copy W image (92160 B = 5760 uint4) ----
    {
        const uint4* wi = reinterpret_cast<const uint4*>(g_wimg_all[layer]);
#pragma unroll
        for (int i = 0; i < 12; i++) {
            int idx = tid + 512 * i;
            if (idx < 5760)
                *reinterpret_cast<uint4*>(sm + SM_WHI + idx * 16) = wi[idx];
        }
    }
    if (tid < 32) reinterpret_cast<float*>(sm + SM_COMP)[tid] = comp[tid];
    if (tid >= 64 && tid < 128)
        reinterpret_cast<float*>(sm + SM_BIASO)[tid - 64] = bias[tid - 64];

    // ---- stage x tile as bf16 hi/lo, stride 72 halfs ----
    const float* xp;
    int xstride;
    if (xin != nullptr) { xp = xin; xstride = 64; }
    else               { xp = g_cs + (layer - 1) * 64; xstride = TDIM; }

    {
        int row  = tid >> 1;
        int half = tid & 1;
        int grow = blockIdx.x * 256 + row;
        const float* xr = xp + (size_t)grow * xstride + half * 32;
        char* xh = sm + SM_XHI + row * 144 + half * 64;
        char* xl = sm + SM_XLO + row * 144 + half * 64;
#pragma unroll
        for (int q = 0; q < 8; q++) {
            float4 v = make_float4(0.f, 0.f, 0.f, 0.f);
            if (grow < NNODE) v = *reinterpret_cast<const float4*>(xr + q * 4);
            __nv_bfloat16 h0 = __float2bfloat16(v.x), h1 = __float2bfloat16(v.y);
            __nv_bfloat16 h2 = __float2bfloat16(v.z), h3 = __float2bfloat16(v.w);
            uint2 hp;
            hp.x = (uint32_t)__bfloat16_as_ushort(h0) | ((uint32_t)__bfloat16_as_ushort(h1) << 16);
            hp.y = (uint32_t)__bfloat16_as_ushort(h2) | ((uint32_t)__bfloat16_as_ushort(h3) << 16);
            __nv_bfloat16 l0 = __float2bfloat16(v.x - __bfloat162float(h0));
            __nv_bfloat16 l1 = __float2bfloat16(v.y - __bfloat162float(h1));
            __nv_bfloat16 l2 = __float2bfloat16(v.z - __bfloat162float(h2));
            __nv_bfloat16 l3 = __float2bfloat16(v.w - __bfloat162float(h3));
            uint2 lp;
            lp.x = (uint32_t)__bfloat16_as_ushort(l0) | ((uint32_t)__bfloat16_as_ushort(l1) << 16);
            lp.y = (uint32_t)__bfloat16_as_ushort(l2) | ((uint32_t)__bfloat16_as_ushort(l3) << 16);
            *reinterpret_cast<uint2*>(xh + q * 8) = hp;
            *reinterpret_cast<uint2*>(xl + q * 8) = lp;
        }
    }
    __syncthreads();

    // ---- per-warp MMA: 16 rows x 320 cols ----
    int lane = tid & 31, wid = tid >> 5;
    int g = lane >> 2, j = lane & 3;
    int lr = wid * 16 + g;
    int grow0 = blockIdx.x * 256 + lr;

    uint32_t Ah[4][4], Al[4][4];
#pragma unroll
    for (int ks = 0; ks < 4; ks++) {
        int c2 = (ks * 16 + 2 * j) * 2;
        Ah[ks][0] = *reinterpret_cast<const uint32_t*>(sm + SM_XHI + lr * 144 + c2);
        Ah[ks][1] = *reinterpret_cast<const uint32_t*>(sm + SM_XHI + (lr + 8) * 144 + c2);
        Ah[ks][2] = *reinterpret_cast<const uint32_t*>(sm + SM_XHI + lr * 144 + c2 + 16);
        Ah[ks][3] = *reinterpret_cast<const uint32_t*>(sm + SM_XHI + (lr + 8) * 144 + c2 + 16);
        Al[ks][0] = *reinterpret_cast<const uint32_t*>(sm + SM_XLO + lr * 144 + c2);
        Al[ks][1] = *reinterpret_cast<const uint32_t*>(sm + SM_XLO + (lr + 8) * 144 + c2);
        Al[ks][2] = *reinterpret_cast<const uint32_t*>(sm + SM_XLO + lr * 144 + c2 + 16);
        Al[ks][3] = *reinterpret_cast<const uint32_t*>(sm + SM_XLO + (lr + 8) * 144 + c2 + 16);
    }

#pragma unroll
    for (int eg = 0; eg < 8; eg++) {
        float acc[4][4];
#pragma unroll
        for (int bt = 0; bt < 4; bt++)
#pragma unroll
            for (int q = 0; q < 4; q++) acc[bt][q] = 0.f;

#pragma unroll
        for (int ks = 0; ks < 4; ks++) {
            int kb2 = (ks * 16 + 2 * j) * 2;
            uint32_t Bh[4][2], Bl[4][2];
#pragma unroll
            for (int bt = 0; bt < 4; bt++) {
                int n = bt * 64 + eg * 8 + g;
                const char* wh = sm + SM_WHI + n * 144 + kb2;
                const char* wl = sm + SM_WLO + n * 144 + kb2;
                Bh[bt][0] = *reinterpret_cast<const uint32_t*>(wh);
                Bh[bt][1] = *reinterpret_cast<const uint32_t*>(wh + 16);
                Bl[bt][0] = *reinterpret_cast<const uint32_t*>(wl);
                Bl[bt][1] = *reinterpret_cast<const uint32_t*>(wl + 16);
            }
#pragma unroll
            for (int bt = 0; bt < 4; bt++) MMA_BF16(acc[bt], Ah[ks], Bh[bt][0], Bh[bt][1]);
#pragma unroll
            for (int bt = 0; bt < 4; bt++) MMA_BF16(acc[bt], Ah[ks], Bl[bt][0], Bl[bt][1]);
#pragma unroll
            for (int bt = 0; bt < 4; bt++) MMA_BF16(acc[bt], Al[ks], Bh[bt][0], Bh[bt][1]);
        }

        unsigned long long p0[4], p1[4];
#pragma unroll
        for (int bt = 0; bt < 4; bt++) {
            p0[bt] = pack_f32x2(acc[bt][0], acc[bt][1]);
            p1[bt] = pack_f32x2(acc[bt][2], acc[bt][3]);
        }
        int e = eg * 8 + 2 * j;
#pragma unroll
        for (int rel = 0; rel < 8; rel++) {
            float4 c4 = *reinterpret_cast<const float4*>(sm + SM_COMP + rel * 16);
            unsigned long long s0 = 0ull, s1 = 0ull;
            ffma2(s0, dup_f32x2(c4.x), p0[0]); ffma2(s1, dup_f32x2(c4.x), p1[0]);
            ffma2(s0, dup_f32x2(c4.y), p0[1]); ffma2(s1, dup_f32x2(c4.y), p1[1]);
            ffma2(s0, dup_f32x2(c4.z), p0[2]); ffma2(s1, dup_f32x2(c4.z), p1[2]);
            ffma2(s0, dup_f32x2(c4.w), p0[3]); ffma2(s1, dup_f32x2(c4.w), p1[3]);
            if (grow0 < NNODE)
                __stcs(reinterpret_cast<float2*>(
                           g_xw + (size_t)grow0 * 512 + rel * 64 + e),
                       *reinterpret_cast<float2*>(&s0));
            if (grow0 + 8 < NNODE)
                __stcs(reinterpret_cast<float2*>(
                           g_xw + (size_t)(grow0 + 8) * 512 + rel * 64 + e),
                       *reinterpret_cast<float2*>(&s1));
        }
    }

    // ---- root columns -> g_agg (+bias) ----
    const float* sb = reinterpret_cast<const float*>(sm + SM_BIASO);
#pragma unroll
    for (int nt = 0; nt < 8; nt++) {
        float acc[4] = {0.f, 0.f, 0.f, 0.f};
#pragma unroll
        for (int ks = 0; ks < 4; ks++) {
            int kb2 = (ks * 16 + 2 * j) * 2;
            int n = 256 + nt * 8 + g;
            const char* wh = sm + SM_WHI + n * 144 + kb2;
            const char* wl = sm + SM_WLO + n * 144 + kb2;
            uint32_t bh0 = *reinterpret_cast<const uint32_t*>(wh);
            uint32_t bh1 = *reinterpret_cast<const uint32_t*>(wh + 16);
            uint32_t bl0 = *reinterpret_cast<const uint32_t*>(wl);
            uint32_t bl1 = *reinterpret_cast<const uint32_t*>(wl + 16);
            MMA_BF16(acc, Ah[ks], bh0, bh1);
            MMA_BF16(acc, Ah[ks], bl0, bl1);
            MMA_BF16(acc, Al[ks], bh0, bh1);
        }
        int e = nt * 8 + 2 * j;
        float b0 = sb[e], b1 = sb[e + 1];
        if (grow0 < NNODE) {
            float2 v = make_float2(acc[0] + b0, acc[1] + b1);
            *reinterpret_cast<float2*>(g_agg + (size_t)grow0 * 64 + e) = v;
        }
        if (grow0 + 8 < NNODE) {
            float2 v = make_float2(acc[2] + b0, acc[3] + b1);
            *reinterpret_cast<float2*>(g_agg + (size_t)(grow0 + 8) * 64 + e) = v;
        }
    }
}

// =====================================================================
// edge_csr: 16 lanes per dst node. acc = g_agg[d] (root+bias), then
// gather+sum xw[src][et] over the dst's incoming edges (4-deep pipeline),
// tanh, write straight into g_cs. No atomics, no finish kernel.
// =====================================================================
__device__ __forceinline__ float4 xw_row(unsigned pk, int j) {
    return __ldcs(reinterpret_cast<const float4*>(
        g_xw + (size_t)(pk & 0xFFFFFu) * 512 + ((pk >> 20) & 7u) * 64 + j * 4));
}

__global__ __launch_bounds__(256) void edge_csr(int rbase, int loff)
{
    int grp = blockIdx.x * 16 + (threadIdx.x >> 4);
    if (grp >= NNODE) return;
    int j = threadIdx.x & 15;

    int beg = __ldg(&g_rowptr[rbase + grp]);
    int end = __ldg(&g_rowptr[rbase + grp + 1]);

    float4 acc = *reinterpret_cast<const float4*>(g_agg + (size_t)grp * 64 + j * 4);

    int e = beg;
    for (; e + 4 <= end; e += 4) {
        unsigned p0 = __ldg(&g_epack[e]);
        unsigned p1 = __ldg(&g_epack[e + 1]);
        unsigned p2 = __ldg(&g_epack[e + 2]);
        unsigned p3 = __ldg(&g_epack[e + 3]);
        float4 v0 = xw_row(p0, j);
        float4 v1 = xw_row(p1, j);
        float4 v2 = xw_row(p2, j);
        float4 v3 = xw_row(p3, j);
        acc.x += (v0.x + v1.x) + (v2.x + v3.x);
        acc.y += (v0.y + v1.y) + (v2.y + v3.y);
        acc.z += (v0.z + v1.z) + (v2.z + v3.z);
        acc.w += (v0.w + v1.w) + (v2.w + v3.w);
    }
    for (; e < end; ++e) {
        float4 v = xw_row(__ldg(&g_epack[e]), j);
        acc.x += v.x; acc.y += v.y; acc.z += v.z; acc.w += v.w;
    }

    acc.x = tanhf(acc.x); acc.y = tanhf(acc.y);
    acc.z = tanhf(acc.z); acc.w = tanhf(acc.w);
    *reinterpret_cast<float4*>(g_cs + (size_t)grp * TDIM + loff + j * 4) = acc;
}

// =====================================================================
// Tail A: gather item_embs_conv + user_emb outputs, build sequence sums.
// =====================================================================
__global__ __launch_bounds__(TDIM) void tail_a(
    const int* __restrict__ users,
    const int* __restrict__ seqs,
    float* __restrict__ out_user,
    float* __restrict__ out_item)
{
    int b = blockIdx.x;
    int t = threadIdx.x;
    float s = 0.f;
#pragma unroll
    for (int j = 0; j < SEQ; j++) {
        int node = __ldg(&seqs[b * SEQ + j]);
        float v  = __ldg(&g_cs[(size_t)node * TDIM + t]);
        out_item[((size_t)b * SEQ + j) * TDIM + t] = v;
        s += v;
    }
    g_ssum[b * TDIM + t] = s;
    int u = __ldg(&users[b]);
    out_user[b * TDIM + t] = __ldg(&g_cs[(size_t)u * TDIM + t]);
}

// =====================================================================
// tb_uv: uv = user_emb + ssum @ WV.  8 batches per block.
// (attention collapses: softmax over query axis => column sums == 1)
// =====================================================================
__global__ __launch_bounds__(TDIM) void tb_uv(
    const float* __restrict__ WV,
    const float* __restrict__ user_emb)
{
    __shared__ float ss[8 * TDIM];
    int b0 = blockIdx.x * 8;
    int t  = threadIdx.x;

#pragma unroll
    for (int i = 0; i < 8; i++)
        ss[i * TDIM + t] = g_ssum[(b0 + i) * TDIM + t];
    __syncthreads();

    float acc[8];
#pragma unroll
    for (int i = 0; i < 8; i++) acc[i] = 0.f;

#pragma unroll 4
    for (int k = 0; k < TDIM; ++k) {
        float w = __ldg(&WV[k * TDIM + t]);
#pragma unroll
        for (int i = 0; i < 8; i++) acc[i] = fmaf(ss[i * TDIM + k], w, acc[i]);
    }
#pragma unroll
    for (int i = 0; i < 8; i++)
        g_uv[(b0 + i) * TDIM + t] = acc[i] + user_emb[(b0 + i) * TDIM + t];
}

// =====================================================================
// tb_res: res[b,k] = pe_w[item]·uv[b] + pe_b[item]
// =====================================================================
__global__ __launch_bounds__(TDIM) void tb_res(
    const float* __restrict__ predict_w,
    const float* __restrict__ predict_b,
    const int*   __restrict__ items,
    float* __restrict__ res)
{
    __shared__ float uv[TDIM];
    int b = blockIdx.x;
    int t = threadIdx.x;
    uv[t] = g_uv[b * TDIM + t];
    __syncthreads();

    int w    = t >> 5;
    int lane = t & 31;
    for (int k = w; k < NPRED; k += TDIM / 32) {
        int it = __ldg(&items[b * NPRED + k]);
        const float* pw = predict_w + (size_t)it * TDIM;
        float s = 0.f;
#pragma unroll
        for (int c = lane; c < TDIM; c += 32) s += __ldg(&pw[c]) * uv[c];
#pragma unroll
        for (int off = 16; off > 0; off >>= 1)
            s += __shfl_down_sync(0xffffffffu, s, off);
        if (lane == 0)
            res[b * NPRED + k] = s + __ldg(&predict_b[it]);
    }
}

// =====================================================================
// Launch
// =====================================================================
extern "C" void kernel_launch(void* const* d_in, const int* in_sizes, int n_in,
                              void* d_out, int out_size)
{
    const float* node_emb  = (const float*)d_in[0];
    const float* predict_w = (const float*)d_in[1];
    const float* predict_b = (const float*)d_in[2];
    const float* basis     = (const float*)d_in[3];
    const float* comp      = (const float*)d_in[4];
    const float* root      = (const float*)d_in[5];
    const float* bias      = (const float*)d_in[6];
    const float* sbasis    = (const float*)d_in[7];
    const float* scomp     = (const float*)d_in[8];
    const float* sroot     = (const float*)d_in[9];
    const float* sbias     = (const float*)d_in[10];
    // d_in[11] = WQ, d_in[12] = WK : provably unused (softmax over query axis)
    const float* WV        = (const float*)d_in[13];
    const int* batch_users = (const int*)d_in[14];
    const int* batch_seq   = (const int*)d_in[15];
    const int* items       = (const int*)d_in[16];
    const int* edge_index  = (const int*)d_in[17];
    const int* edge_type   = (const int*)d_in[18];
    // d_in[19] = node_no (identity gather, unused)
    const int* sedge_index = (const int*)d_in[20];
    const int* sedge_type  = (const int*)d_in[21];

    const int E  = in_sizes[18];   // 1,000,000
    const int SE = in_sizes[21];   //   200,000

    const int* srcB = edge_index;
    const int* dstB = edge_index + E;
    const int* srcS = sedge_index;
    const int* dstS = sedge_index + SE;

    float* out_res  = (float*)d_out;                       // [1024][20]
    float* out_user = out_res + BATCH * NPRED;             // [1024][384]
    float* out_item = out_user + BATCH * TDIM;             // [1024][20][384]

    cudaFuncSetAttribute(tc_dense,
                         cudaFuncAttributeMaxDynamicSharedMemorySize, TC_SMEM);

    // ---- one-time prep: W images + CSR for both graphs ----
    w_prep_all<<<480, 256>>>(basis, root, sbasis, sroot);
    csr_zero<<<NSCANB, 1024>>>();
    csr_hist<<<(E + SE + 255) / 256, 256>>>(dstB, dstS, E, SE);
    csr_scan1<<<NSCANB, 1024>>>();
    csr_scan2<<<1, 32>>>();
    csr_scan3<<<NSCANB, 1024>>>();
    csr_scatter<<<(E + SE + 255) / 256, 256>>>(srcB, dstB, edge_type,
                                               srcS, dstS, sedge_type, E, SE);

    const int tc_grid  = (NNODE + 255) / 256;              // 586
    const int csr_grid = (NNODE + 15) / 16;                // 9375

    for (int l = 0; l < 6; ++l) {
        bool big = (l < 3);
        int  ll  = big ? l : l - 3;
        const float* Bi = (big ? bias : sbias) + ll * 64;
        const float* C  = (big ? comp : scomp) + ll * 32;
        const float* xi = (l == 0) ? node_emb : nullptr;
        int rbase       = big ? 0 : (NNODE + 1);

        tc_dense<<<tc_grid, 512, TC_SMEM>>>(xi, l, C, Bi);
        edge_csr<<<csr_grid, 256>>>(rbase, l * 64);
    }

    tail_a<<<BATCH, TDIM>>>(batch_users, batch_seq, out_user, out_item);
    tb_uv<<<BATCH / 8, TDIM>>>(WV, out_user);
    tb_res<<<BATCH, TDIM>>>(predict_w, predict_b, items, out_res);
}